// round 7
// baseline (speedup 1.0000x reference)
#include <cuda_runtime.h>
#include <cuda_bf16.h>
#include <cstdint>

// Problem constants (fixed by the reference: B=8, C=512, T=2048)
#define NB 8
#define NC 512
#define NT 2048

// ---------------- scratch (device globals; no allocation allowed) ----------
__device__ __nv_bfloat16 g_xt  [(size_t)NB * NT * NC];      // x^T [B,T,C]
__device__ __nv_bfloat16 g_qk  [(size_t)NB * NT * 2 * NC];  // theta^T || phi^T [B,T,2C]
__device__ __nv_bfloat16 g_g   [(size_t)NB * NC * NT];      // g [B,C,T]
__device__ __nv_bfloat16 g_feat[(size_t)NB * NT * NC];      // feat^T [B,T,C]
__device__ __nv_bfloat16 g_wbf [4 * (size_t)NC * NC];       // wT|wP|wG|wW bf16
__device__ float         g_bqk [2 * NC];                    // b_theta || b_phi

// ---------------- helpers ---------------------------------------------------
__device__ __forceinline__ uint32_t smem_u32(const void* p) {
    return (uint32_t)__cvta_generic_to_shared(p);
}
__device__ __forceinline__ void cpa16u(uint32_t dst, const void* src) {
    asm volatile("cp.async.cg.shared.global [%0], [%1], 16;" :: "r"(dst), "l"(src));
}
__device__ __forceinline__ void cpa_commit() {
    asm volatile("cp.async.commit_group;" ::: "memory");
}
template<int N>
__device__ __forceinline__ void cpa_wait() {
    asm volatile("cp.async.wait_group %0;" :: "n"(N) : "memory");
}
__device__ __forceinline__ void ldsm4(uint32_t* r, uint32_t addr) {
    asm volatile("ldmatrix.sync.aligned.m8n8.x4.shared.b16 {%0,%1,%2,%3}, [%4];"
                 : "=r"(r[0]), "=r"(r[1]), "=r"(r[2]), "=r"(r[3]) : "r"(addr));
}
__device__ __forceinline__ void mma16(float* d, const uint32_t* a, const uint32_t* b) {
    asm volatile(
        "mma.sync.aligned.m16n8k16.row.col.f32.bf16.bf16.f32 "
        "{%0,%1,%2,%3}, {%4,%5,%6,%7}, {%8,%9}, {%0,%1,%2,%3};"
        : "+f"(d[0]), "+f"(d[1]), "+f"(d[2]), "+f"(d[3])
        : "r"(a[0]), "r"(a[1]), "r"(a[2]), "r"(a[3]), "r"(b[0]), "r"(b[1]));
}
__device__ __forceinline__ __nv_bfloat16 bfr(float f) { return __float2bfloat16_rn(f); }

// ---------------- BF16 GEMM: C[M,N] = sum_k A[m,k] * B[n,k] ------------------
// EPI: 1 relu(acc+bias[m]) | 2 relu(acc+bias[n]) | 3 relu(acc+bias[m])+res
// OBF: store bf16 (else fp32).  CTA tile 256x128x32, 8 warps of 64x64.
template<int EPI, bool OBF>
__global__ void __launch_bounds__(256, 1)
gemm_bf(const __nv_bfloat16* __restrict__ A, const __nv_bfloat16* __restrict__ B,
        void* __restrict__ outv, int lda, int ldb, int ldo, int K,
        long long sA, long long sB, long long sO,
        const float* __restrict__ bias,
        const float* __restrict__ res, long long sR)
{
    constexpr int BM = 256, BN = 128, BK = 32, NSTG = 3;
    constexpr int LDE = 40;
    constexpr int A_BYT = BM * LDE * 2;
    constexpr int B_BYT = BN * LDE * 2;

    extern __shared__ char dsm[];
    const uint32_t smA = smem_u32(dsm);
    const uint32_t smB = smA + NSTG * A_BYT;

    const int tid = threadIdx.x;
    const int bn = blockIdx.x, bm = blockIdx.y, bz = blockIdx.z;
    const int warp = tid >> 5, lane = tid & 31;
    const int wm = warp >> 1, wn = warp & 1;
    const int r = lane & 3, q = lane >> 2;

    A += (long long)bz * sA + (long long)bm * BM * lda;
    B += (long long)bz * sB + (long long)bn * BN * ldb;
    if constexpr (EPI == 3) res += (long long)bz * sR;

    const int rowA = (lane & 7) + ((lane >> 3) & 1) * 8;
    const int kcA  = ((lane >> 4) & 1) * 8;
    const int rowB = (lane & 7) + ((lane >> 4) & 1) * 8;
    const int kcB  = ((lane >> 3) & 1) * 8;

    float acc[4][8][4];
    #pragma unroll
    for (int i = 0; i < 4; i++)
        #pragma unroll
        for (int j = 0; j < 8; j++)
            #pragma unroll
            for (int c = 0; c < 4; c++) acc[i][j][c] = 0.f;

    auto load_stage = [&](int kt, int sb) {
        const char* Ag = (const char*)A + (long long)kt * BK * 2;
        const char* Bg = (const char*)B + (long long)kt * BK * 2;
        const uint32_t as = smA + sb * A_BYT;
        const uint32_t bs = smB + sb * B_BYT;
        #pragma unroll
        for (int i = 0; i < 4; i++) {
            const int id = tid + i * 256;
            const int row = id >> 2, c = (id & 3) * 16;
            cpa16u(as + row * 80 + c, Ag + (long long)row * lda * 2 + c);
        }
        #pragma unroll
        for (int i = 0; i < 2; i++) {
            const int id = tid + i * 256;
            const int row = id >> 2, c = (id & 3) * 16;
            cpa16u(bs + row * 80 + c, Bg + (long long)row * ldb * 2 + c);
        }
    };

    const int nk = K / BK;
    load_stage(0, 0); cpa_commit();
    load_stage(1, 1); cpa_commit();

    for (int kt = 0; kt < nk; ++kt) {
        cpa_wait<1>();
        __syncthreads();
        if (kt + 2 < nk) load_stage(kt + 2, (kt + 2) % NSTG);
        cpa_commit();

        const uint32_t aA = smA + (kt % NSTG) * A_BYT;
        const uint32_t aB = smB + (kt % NSTG) * B_BYT;

        #pragma unroll
        for (int ks = 0; ks < 2; ++ks) {
            const int kk = ks * 16;
            uint32_t af[4][4], bf[8][2];
            #pragma unroll
            for (int mt = 0; mt < 4; ++mt)
                ldsm4(af[mt], aA + ((wm * 64 + mt * 16 + rowA) * LDE + kcA + kk) * 2);
            #pragma unroll
            for (int ntp = 0; ntp < 4; ++ntp) {
                uint32_t t4[4];
                ldsm4(t4, aB + ((wn * 64 + ntp * 16 + rowB) * LDE + kcB + kk) * 2);
                bf[2 * ntp + 0][0] = t4[0]; bf[2 * ntp + 0][1] = t4[1];
                bf[2 * ntp + 1][0] = t4[2]; bf[2 * ntp + 1][1] = t4[3];
            }
            #pragma unroll
            for (int mt = 0; mt < 4; ++mt)
                #pragma unroll
                for (int nt = 0; nt < 8; ++nt)
                    mma16(acc[mt][nt], af[mt], bf[nt]);
        }
    }

    #pragma unroll
    for (int mt = 0; mt < 4; ++mt) {
        #pragma unroll
        for (int h = 0; h < 2; ++h) {
            const int row = bm * BM + wm * 64 + mt * 16 + h * 8 + q;
            float bv = 0.f;
            if constexpr (EPI == 1 || EPI == 3) bv = bias[row];
            const long long obase = (long long)bz * sO + (long long)row * ldo;
            #pragma unroll
            for (int nt = 0; nt < 8; ++nt) {
                const int gn = bn * BN + wn * 64 + nt * 8 + 2 * r;
                float c0 = acc[mt][nt][2 * h + 0];
                float c1 = acc[mt][nt][2 * h + 1];
                if constexpr (EPI == 1 || EPI == 3) {
                    c0 = fmaxf(c0 + bv, 0.f);
                    c1 = fmaxf(c1 + bv, 0.f);
                } else if constexpr (EPI == 2) {
                    c0 = fmaxf(c0 + bias[gn], 0.f);
                    c1 = fmaxf(c1 + bias[gn + 1], 0.f);
                }
                if constexpr (EPI == 3) {
                    const float* rp = res + (long long)row * ldo + gn;
                    c0 += rp[0]; c1 += rp[1];
                }
                if constexpr (OBF) {
                    __nv_bfloat162 v; v.x = bfr(c0); v.y = bfr(c1);
                    *(__nv_bfloat162*)((__nv_bfloat16*)outv + obase + gn) = v;
                } else {
                    float2 v; v.x = c0; v.y = c1;
                    *(float2*)((float*)outv + obase + gn) = v;
                }
            }
        }
    }
}

// ---------------- flash: feat^T[i,c] = softmax_j(theta_i . phi_j) @ g --------
// Q = thph[b, i, 0:512], K = thph[b, j, 512:1024], V = g[b, c, j].
// CTA: 64 q rows, 256 threads, 8 warps (4m x 2n). 16 kv chunks of 128.
__global__ void __launch_bounds__(256, 1)
flash_attn(const __nv_bfloat16* __restrict__ thph,
           const __nv_bfloat16* __restrict__ V,
           __nv_bfloat16* __restrict__ Oout)
{
    constexpr int LDQ = 520, LDK = 72, LDV = 136, LDP = 136;
    constexpr int STG_B = 128 * LDK * 2;            // 18432 per stage
    constexpr int Q_B = 64 * LDQ * 2;               // 66560
    extern __shared__ char sm[];
    char* sQ   = sm;
    char* sStg = sm + Q_B;
    char* sP   = sm + Q_B + 3 * STG_B;
    __shared__ float redm[2][64], reds[2][64];

    const int tid = threadIdx.x, warp = tid >> 5, lane = tid & 31;
    const int wm = warp >> 1, wn = warp & 1;
    const int r = lane & 3, q8 = lane >> 2;
    const int bq = blockIdx.x, bz = blockIdx.y;

    const __nv_bfloat16* Qg = thph + ((size_t)bz * NT + bq * 64) * (2 * NC);
    const __nv_bfloat16* Kg = thph + (size_t)bz * NT * (2 * NC) + NC;
    const __nv_bfloat16* Vg = V + (size_t)bz * NC * NT;

    const int rowA = (lane & 7) + ((lane >> 3) & 1) * 8;
    const int kcA  = ((lane >> 4) & 1) * 8;
    const int rowB = (lane & 7) + ((lane >> 4) & 1) * 8;
    const int kcB  = ((lane >> 3) & 1) * 8;
    const int row0 = wm * 16 + q8, row1 = row0 + 8;

    auto issue_slice = [&](int t) {
        const int j = t >> 4, ph = t & 15;
        const uint32_t dst = smem_u32(sStg + (t % 3) * STG_B);
        if (ph < 8) {                 // K slice: 128 kv rows x 64 c
            const char* src = (const char*)(Kg + ((size_t)j * 128) * 2 * NC + ph * 64);
            #pragma unroll
            for (int i = 0; i < 4; i++) {
                const int id = tid + i * 256;
                const int row = id >> 3, c = (id & 7) * 16;
                cpa16u(dst + row * (LDK * 2) + c, src + (size_t)row * 4 * NC + c);
            }
        } else {                      // V slice: 64 c rows x 128 kv
            const int s = ph - 8;
            const char* src = (const char*)(Vg + (size_t)(s * 64) * NT + j * 128);
            #pragma unroll
            for (int i = 0; i < 4; i++) {
                const int id = tid + i * 256;
                const int row = id >> 4, c = (id & 15) * 16;
                cpa16u(dst + row * (LDV * 2) + c, src + (size_t)row * 2 * NT + c);
            }
        }
    };

    // prologue: group0 = {Q, slice0}, group1 = {slice1}
    {
        const uint32_t dq = smem_u32(sQ);
        #pragma unroll
        for (int i = 0; i < 16; i++) {
            const int id = tid + i * 256;
            const int row = id >> 6, c = (id & 63) * 16;
            cpa16u(dq + row * (LDQ * 2) + c, (const char*)(Qg + (size_t)row * 2 * NC) + c);
        }
        issue_slice(0); cpa_commit();
        issue_slice(1); cpa_commit();
    }

    float oacc[32][4];
    #pragma unroll
    for (int i = 0; i < 32; i++)
        #pragma unroll
        for (int c = 0; c < 4; c++) oacc[i][c] = 0.f;
    float sacc[8][4];
    float m0 = -1e30f, m1 = -1e30f, l0 = 0.f, l1 = 0.f;

    auto pipe = [&](int t) {
        cpa_wait<1>();
        __syncthreads();
        if (t + 2 < 256) issue_slice(t + 2);
        cpa_commit();
    };

    #pragma unroll 1
    for (int j = 0; j < 16; ++j) {
        // ---- QK: S[64 x 128] += Q . K^T over 8 c-slices ----
        #pragma unroll 1
        for (int cc = 0; cc < 8; ++cc) {
            const int t = j * 16 + cc;
            pipe(t);
            if (cc == 0) {
                #pragma unroll
                for (int nt = 0; nt < 8; nt++)
                    #pragma unroll
                    for (int c = 0; c < 4; c++) sacc[nt][c] = 0.f;
            }
            const uint32_t aQ = smem_u32(sQ);
            const uint32_t aK = smem_u32(sStg + (t % 3) * STG_B);
            #pragma unroll
            for (int ks = 0; ks < 4; ++ks) {
                uint32_t af[4];
                ldsm4(af, aQ + ((wm * 16 + rowA) * LDQ + cc * 64 + ks * 16 + kcA) * 2);
                uint32_t bf[8][2];
                #pragma unroll
                for (int ntp = 0; ntp < 4; ++ntp) {
                    uint32_t t4[4];
                    ldsm4(t4, aK + ((wn * 64 + ntp * 16 + rowB) * LDK + ks * 16 + kcB) * 2);
                    bf[2 * ntp + 0][0] = t4[0]; bf[2 * ntp + 0][1] = t4[1];
                    bf[2 * ntp + 1][0] = t4[2]; bf[2 * ntp + 1][1] = t4[3];
                }
                #pragma unroll
                for (int nt = 0; nt < 8; ++nt) mma16(sacc[nt], af, bf[nt]);
            }
        }
        // ---- PV over 8 c-slices; online softmax before the first ----
        #pragma unroll 1
        for (int s = 0; s < 8; ++s) {
            const int t = j * 16 + 8 + s;
            pipe(t);
            if (s == 0) {
                // --- online softmax on sacc ---
                float pm0 = -1e30f, pm1 = -1e30f;
                #pragma unroll
                for (int nt = 0; nt < 8; ++nt) {
                    pm0 = fmaxf(pm0, fmaxf(sacc[nt][0], sacc[nt][1]));
                    pm1 = fmaxf(pm1, fmaxf(sacc[nt][2], sacc[nt][3]));
                }
                pm0 = fmaxf(pm0, __shfl_xor_sync(0xffffffffu, pm0, 1));
                pm0 = fmaxf(pm0, __shfl_xor_sync(0xffffffffu, pm0, 2));
                pm1 = fmaxf(pm1, __shfl_xor_sync(0xffffffffu, pm1, 1));
                pm1 = fmaxf(pm1, __shfl_xor_sync(0xffffffffu, pm1, 2));
                if (r == 0) { redm[wn][row0] = pm0; redm[wn][row1] = pm1; }
                __syncthreads();
                const float nm0 = fmaxf(m0, fmaxf(redm[0][row0], redm[1][row0]));
                const float nm1 = fmaxf(m1, fmaxf(redm[0][row1], redm[1][row1]));
                const float sc0 = __expf(m0 - nm0), sc1 = __expf(m1 - nm1);
                m0 = nm0; m1 = nm1;
                float ps0 = 0.f, ps1 = 0.f;
                __nv_bfloat16* P0 = (__nv_bfloat16*)sP + row0 * LDP + wn * 64 + 2 * r;
                __nv_bfloat16* P1 = (__nv_bfloat16*)sP + row1 * LDP + wn * 64 + 2 * r;
                #pragma unroll
                for (int nt = 0; nt < 8; ++nt) {
                    const float p0 = __expf(sacc[nt][0] - m0);
                    const float p1 = __expf(sacc[nt][1] - m0);
                    const float p2 = __expf(sacc[nt][2] - m1);
                    const float p3 = __expf(sacc[nt][3] - m1);
                    ps0 += p0 + p1; ps1 += p2 + p3;
                    __nv_bfloat162 u; u.x = bfr(p0); u.y = bfr(p1);
                    *(__nv_bfloat162*)(P0 + nt * 8) = u;
                    __nv_bfloat162 w; w.x = bfr(p2); w.y = bfr(p3);
                    *(__nv_bfloat162*)(P1 + nt * 8) = w;
                }
                ps0 += __shfl_xor_sync(0xffffffffu, ps0, 1);
                ps0 += __shfl_xor_sync(0xffffffffu, ps0, 2);
                ps1 += __shfl_xor_sync(0xffffffffu, ps1, 1);
                ps1 += __shfl_xor_sync(0xffffffffu, ps1, 2);
                if (r == 0) { reds[wn][row0] = ps0; reds[wn][row1] = ps1; }
                #pragma unroll
                for (int i = 0; i < 32; i++) {
                    oacc[i][0] *= sc0; oacc[i][1] *= sc0;
                    oacc[i][2] *= sc1; oacc[i][3] *= sc1;
                }
                __syncthreads();   // P visible + reds ready
                l0 = l0 * sc0 + reds[0][row0] + reds[1][row0];
                l1 = l1 * sc1 + reds[0][row1] + reds[1][row1];
            }
            const uint32_t aP = smem_u32(sP);
            const uint32_t aV = smem_u32(sStg + (t % 3) * STG_B);
            #pragma unroll
            for (int ks = 0; ks < 8; ++ks) {
                uint32_t af[4];
                ldsm4(af, aP + ((wm * 16 + rowA) * LDP + ks * 16 + kcA) * 2);
                uint32_t bv[4][2];
                #pragma unroll
                for (int ntp = 0; ntp < 2; ++ntp) {
                    uint32_t t4[4];
                    ldsm4(t4, aV + ((wn * 32 + ntp * 16 + rowB) * LDV + ks * 16 + kcB) * 2);
                    bv[2 * ntp + 0][0] = t4[0]; bv[2 * ntp + 0][1] = t4[1];
                    bv[2 * ntp + 1][0] = t4[2]; bv[2 * ntp + 1][1] = t4[3];
                }
                #pragma unroll
                for (int nt = 0; nt < 4; ++nt) mma16(oacc[s * 4 + nt], af, bv[nt]);
            }
        }
    }

    // ---- epilogue: O /= l, store bf16 ----
    const float inv0 = 1.f / l0, inv1 = 1.f / l1;
    __nv_bfloat16* Ob = Oout + ((size_t)bz * NT + bq * 64) * NC;
    #pragma unroll
    for (int s = 0; s < 8; ++s)
        #pragma unroll
        for (int nt = 0; nt < 4; ++nt) {
            const int i = s * 4 + nt;
            const int c = s * 64 + wn * 32 + nt * 8 + 2 * r;
            __nv_bfloat162 u; u.x = bfr(oacc[i][0] * inv0); u.y = bfr(oacc[i][1] * inv0);
            *(__nv_bfloat162*)(Ob + (size_t)row0 * NC + c) = u;
            __nv_bfloat162 w; w.x = bfr(oacc[i][2] * inv1); w.y = bfr(oacc[i][3] * inv1);
            *(__nv_bfloat162*)(Ob + (size_t)row1 * NC + c) = w;
        }
}

// ---------------- x transpose: [B,C,T] fp32 -> [B,T,C] bf16 ------------------
__global__ void __launch_bounds__(256, 4)
transpose_x(const float* __restrict__ x, __nv_bfloat16* __restrict__ xt)
{
    __shared__ float s[32][33];
    const int bz = blockIdx.z;
    const float* xp = x + (size_t)bz * NC * NT;
    __nv_bfloat16* op = xt + (size_t)bz * NT * NC;
    const int c0 = blockIdx.y * 32, t0 = blockIdx.x * 32;
    const int tid = threadIdx.x;
    {
        const int c = tid >> 3, tq = (tid & 7) * 4;
        float4 v = *(const float4*)&xp[(size_t)(c0 + c) * NT + t0 + tq];
        s[c][tq + 0] = v.x; s[c][tq + 1] = v.y;
        s[c][tq + 2] = v.z; s[c][tq + 3] = v.w;
    }
    __syncthreads();
    {
        const int t = tid >> 3, cb = (tid & 7) * 4;
        __nv_bfloat162 u0, u1;
        u0.x = bfr(s[cb + 0][t]); u0.y = bfr(s[cb + 1][t]);
        u1.x = bfr(s[cb + 2][t]); u1.y = bfr(s[cb + 3][t]);
        __nv_bfloat16* o = &op[(size_t)(t0 + t) * NC + c0 + cb];
        *(__nv_bfloat162*)(o + 0) = u0;
        *(__nv_bfloat162*)(o + 2) = u1;
    }
}

// ---------------- prep: all 4 weights -> bf16, stack theta/phi bias ----------
__global__ void __launch_bounds__(256, 8)
prep(const float* __restrict__ w0, const float* __restrict__ w1,
     const float* __restrict__ w2, const float* __restrict__ w3,
     const float* __restrict__ bt, const float* __restrict__ bp,
     __nv_bfloat16* __restrict__ wo, float* __restrict__ bqk)
{
    const int i = blockIdx.x * 256 + threadIdx.x;   // [0, 262144)
    const int idx = i * 4;
    const float* srcs[4] = {w0, w1, w2, w3};
    const float* sp = srcs[idx >> 18];
    float4 v = *(const float4*)(sp + (idx & 0x3FFFF));
    __nv_bfloat162 a, b;
    a.x = bfr(v.x); a.y = bfr(v.y);
    b.x = bfr(v.z); b.y = bfr(v.w);
    *(__nv_bfloat162*)(wo + idx)     = a;
    *(__nv_bfloat162*)(wo + idx + 2) = b;
    if (i < 2 * NC) bqk[i] = (i < NC) ? bt[i] : bp[i - NC];
}

// ---------------- launch ----------------------------------------------------
extern "C" void kernel_launch(void* const* d_in, const int* in_sizes, int n_in,
                              void* d_out, int out_size)
{
    const float* x       = (const float*)d_in[0];
    const float* w_theta = (const float*)d_in[1];
    const float* b_theta = (const float*)d_in[2];
    const float* w_phi   = (const float*)d_in[3];
    const float* b_phi   = (const float*)d_in[4];
    const float* w_g     = (const float*)d_in[5];
    const float* b_g     = (const float*)d_in[6];
    const float* w_w     = (const float*)d_in[7];
    const float* b_w     = (const float*)d_in[8];

    void *pxt, *pqk, *pg, *pf, *pw, *pb;
    cudaGetSymbolAddress(&pxt, g_xt);
    cudaGetSymbolAddress(&pqk, g_qk);
    cudaGetSymbolAddress(&pg,  g_g);
    cudaGetSymbolAddress(&pf,  g_feat);
    cudaGetSymbolAddress(&pw,  g_wbf);
    cudaGetSymbolAddress(&pb,  g_bqk);
    __nv_bfloat16* xt   = (__nv_bfloat16*)pxt;
    __nv_bfloat16* thph = (__nv_bfloat16*)pqk;
    __nv_bfloat16* gg   = (__nv_bfloat16*)pg;
    __nv_bfloat16* ft   = (__nv_bfloat16*)pf;
    __nv_bfloat16* wbf  = (__nv_bfloat16*)pw;
    float*         bqk  = (float*)pb;
    __nv_bfloat16* wG = wbf + 2 * (size_t)NC * NC;
    __nv_bfloat16* wW = wbf + 3 * (size_t)NC * NC;

    const long long sCT = (long long)NC * NT;

    auto kconvT = gemm_bf<2, true >;   // stacked theta/phi: col bias
    auto kconvG = gemm_bf<1, true >;   // g: row bias
    auto kfinal = gemm_bf<3, false>;   // relu(W.f+b)+x, fp32 out

    const int SMEM = 3 * (20480 + 10240);   // 92160
    cudaFuncSetAttribute(kconvT, cudaFuncAttributeMaxDynamicSharedMemorySize, SMEM);
    cudaFuncSetAttribute(kconvG, cudaFuncAttributeMaxDynamicSharedMemorySize, SMEM);
    cudaFuncSetAttribute(kfinal, cudaFuncAttributeMaxDynamicSharedMemorySize, SMEM);
    const int FSM = 64 * 520 * 2 + 3 * (128 * 72 * 2) + 64 * 136 * 2;  // 139264
    cudaFuncSetAttribute(flash_attn, cudaFuncAttributeMaxDynamicSharedMemorySize, FSM);

    dim3 blk(256);

    // 0) weights -> bf16 (+ stacked bias); x -> x^T bf16
    prep<<<1024, blk>>>(w_theta, w_phi, w_g, w_w, b_theta, b_phi, wbf, bqk);
    transpose_x<<<dim3(NT / 32, NC / 32, NB), blk>>>(x, xt);

    // 1) thph[t, 0:1024] = relu(xt . [Wt|Wp]^T + [bt|bp])   (M=T, N=2C)
    kconvT<<<dim3(2 * NC / 128, NT / 256, NB), blk, SMEM>>>(
        xt, wbf, thph, NC, NC, 2 * NC, NC, sCT, 0, (long long)NT * 2 * NC,
        bqk, nullptr, 0);

    // 2) g[o,t] = relu(Wg . x + b)                           (M=C, N=T)
    kconvG<<<dim3(NT / 128, NC / 256, NB), blk, SMEM>>>(
        wG, xt, gg, NC, NC, NT, NC, 0, sCT, sCT, b_g, nullptr, 0);

    // 3) fused scores + softmax + feature
    flash_attn<<<dim3(NT / 64, NB), blk, FSM>>>(thph, gg, ft);

    // 4) out = relu(Ww . feat + b) + x                       (M=C, N=T)
    kfinal<<<dim3(NT / 128, NC / 256, NB), blk, SMEM>>>(
        wW, ft, d_out, NC, NC, NT, NC, 0, sCT, sCT, b_w, x, sCT);
}

// round 8
// speedup vs baseline: 1.6290x; 1.6290x over previous
#include <cuda_runtime.h>
#include <cuda_bf16.h>
#include <cstdint>

// Problem constants (fixed by the reference: B=8, C=512, T=2048)
#define NB 8
#define NC 512
#define NT 2048

// ---------------- scratch (device globals; no allocation allowed) ----------
__device__ __nv_bfloat16 g_xt  [(size_t)NB * NT * NC];      // x^T [B,T,C]
__device__ __nv_bfloat16 g_qk  [(size_t)NB * NT * 2 * NC];  // theta^T || phi^T [B,T,2C]
__device__ __nv_bfloat16 g_g   [(size_t)NB * NC * NT];      // g [B,C,T]
__device__ __nv_bfloat16 g_feat[(size_t)NB * NT * NC];      // feat^T [B,T,C]
__device__ __nv_bfloat16 g_attn[(size_t)NB * NT * NT];      // attn [B,T,T]
__device__ float         g_sc  [(size_t)NB * NT * NT];      // scores [B,T,T] fp32
__device__ __nv_bfloat16 g_wbf [4 * (size_t)NC * NC];       // wT|wP|wG|wW bf16
__device__ float         g_bqk [2 * NC];                    // b_theta || b_phi

// ---------------- helpers ---------------------------------------------------
__device__ __forceinline__ uint32_t smem_u32(const void* p) {
    return (uint32_t)__cvta_generic_to_shared(p);
}
__device__ __forceinline__ void cpa16u(uint32_t dst, const void* src) {
    asm volatile("cp.async.cg.shared.global [%0], [%1], 16;" :: "r"(dst), "l"(src));
}
__device__ __forceinline__ void cpa_commit() {
    asm volatile("cp.async.commit_group;" ::: "memory");
}
template<int N>
__device__ __forceinline__ void cpa_wait() {
    asm volatile("cp.async.wait_group %0;" :: "n"(N) : "memory");
}
__device__ __forceinline__ void ldsm4(uint32_t* r, uint32_t addr) {
    asm volatile("ldmatrix.sync.aligned.m8n8.x4.shared.b16 {%0,%1,%2,%3}, [%4];"
                 : "=r"(r[0]), "=r"(r[1]), "=r"(r[2]), "=r"(r[3]) : "r"(addr));
}
__device__ __forceinline__ void mma16(float* d, const uint32_t* a, const uint32_t* b) {
    asm volatile(
        "mma.sync.aligned.m16n8k16.row.col.f32.bf16.bf16.f32 "
        "{%0,%1,%2,%3}, {%4,%5,%6,%7}, {%8,%9}, {%0,%1,%2,%3};"
        : "+f"(d[0]), "+f"(d[1]), "+f"(d[2]), "+f"(d[3])
        : "r"(a[0]), "r"(a[1]), "r"(a[2]), "r"(a[3]), "r"(b[0]), "r"(b[1]));
}
__device__ __forceinline__ __nv_bfloat16 bfr(float f) { return __float2bfloat16_rn(f); }

// ---------------- BF16 GEMM: C[M,N] = sum_k A[m,k] * B[n,k] ------------------
// A: [M,K] bf16 (k contiguous), B: [N,K] bf16 (k contiguous)
// EPI: 0 plain | 1 relu(acc+bias[m]) | 2 relu(acc+bias[n]) | 3 relu(acc+bias[m])+res
// OBF: store bf16 (else fp32).
// CTA tile 128x128x32, 8 warps of 32x64, 2 CTAs/SM (regs capped at 128).
template<int EPI, bool OBF>
__global__ void __launch_bounds__(256, 2)
gemm_bf(const __nv_bfloat16* __restrict__ A, const __nv_bfloat16* __restrict__ B,
        void* __restrict__ outv, int lda, int ldb, int ldo, int K,
        long long sA, long long sB, long long sO,
        const float* __restrict__ bias,
        const float* __restrict__ res, long long sR)
{
    constexpr int BM = 128, BN = 128, BK = 32, NSTG = 3;
    constexpr int LDE = 40;                 // smem row stride (80 B = 5*16B banks)
    constexpr int A_BYT = BM * LDE * 2;     // 10240
    constexpr int B_BYT = BN * LDE * 2;     // 10240

    extern __shared__ char dsm[];
    const uint32_t smA = smem_u32(dsm);
    const uint32_t smB = smA + NSTG * A_BYT;

    const int tid = threadIdx.x;
    const int bn = blockIdx.x, bm = blockIdx.y, bz = blockIdx.z;
    const int warp = tid >> 5, lane = tid & 31;
    const int wm = warp >> 1, wn = warp & 1;     // 4 x 2 warps, 32x64 each
    const int r = lane & 3, q = lane >> 2;

    A += (long long)bz * sA + (long long)bm * BM * lda;
    B += (long long)bz * sB + (long long)bn * BN * ldb;
    if constexpr (EPI == 3) res += (long long)bz * sR;

    const int rowA = (lane & 7) + ((lane >> 3) & 1) * 8;   // bit3 = m-high
    const int kcA  = ((lane >> 4) & 1) * 8;                // bit4 = k-high
    const int rowB = (lane & 7) + ((lane >> 4) & 1) * 8;   // bit4 = n-high
    const int kcB  = ((lane >> 3) & 1) * 8;                // bit3 = k-high

    float acc[2][8][4];
    #pragma unroll
    for (int i = 0; i < 2; i++)
        #pragma unroll
        for (int j = 0; j < 8; j++)
            #pragma unroll
            for (int c = 0; c < 4; c++) acc[i][j][c] = 0.f;

    auto load_stage = [&](int kt, int sb) {
        const char* Ag = (const char*)A + (long long)kt * BK * 2;
        const char* Bg = (const char*)B + (long long)kt * BK * 2;
        const uint32_t as = smA + sb * A_BYT;
        const uint32_t bs = smB + sb * B_BYT;
        #pragma unroll
        for (int i = 0; i < 2; i++) {           // A: 128 rows x 64B
            const int id = tid + i * 256;
            const int row = id >> 2, c = (id & 3) * 16;
            cpa16u(as + row * 80 + c, Ag + (long long)row * lda * 2 + c);
        }
        #pragma unroll
        for (int i = 0; i < 2; i++) {           // B: 128 rows x 64B
            const int id = tid + i * 256;
            const int row = id >> 2, c = (id & 3) * 16;
            cpa16u(bs + row * 80 + c, Bg + (long long)row * ldb * 2 + c);
        }
    };

    const int nk = K / BK;
    load_stage(0, 0); cpa_commit();
    load_stage(1, 1); cpa_commit();

    for (int kt = 0; kt < nk; ++kt) {
        cpa_wait<1>();
        __syncthreads();
        if (kt + 2 < nk) load_stage(kt + 2, (kt + 2) % NSTG);
        cpa_commit();

        const uint32_t aA = smA + (kt % NSTG) * A_BYT;
        const uint32_t aB = smB + (kt % NSTG) * B_BYT;

        #pragma unroll
        for (int ks = 0; ks < 2; ++ks) {
            const int kk = ks * 16;
            uint32_t af[2][4], bf[8][2];
            #pragma unroll
            for (int mt = 0; mt < 2; ++mt)
                ldsm4(af[mt], aA + ((wm * 32 + mt * 16 + rowA) * LDE + kcA + kk) * 2);
            #pragma unroll
            for (int ntp = 0; ntp < 4; ++ntp) {
                uint32_t t4[4];
                ldsm4(t4, aB + ((wn * 64 + ntp * 16 + rowB) * LDE + kcB + kk) * 2);
                bf[2 * ntp + 0][0] = t4[0]; bf[2 * ntp + 0][1] = t4[1];
                bf[2 * ntp + 1][0] = t4[2]; bf[2 * ntp + 1][1] = t4[3];
            }
            #pragma unroll
            for (int mt = 0; mt < 2; ++mt)
                #pragma unroll
                for (int nt = 0; nt < 8; ++nt)
                    mma16(acc[mt][nt], af[mt], bf[nt]);
        }
    }

    // ---- epilogue: c0,c1 -> (row q, cols 2r,2r+1); c2,c3 -> row q+8 ---------
    #pragma unroll
    for (int mt = 0; mt < 2; ++mt) {
        #pragma unroll
        for (int h = 0; h < 2; ++h) {
            const int row = bm * BM + wm * 32 + mt * 16 + h * 8 + q;
            float bv = 0.f;
            if constexpr (EPI == 1 || EPI == 3) bv = bias[row];
            const long long obase = (long long)bz * sO + (long long)row * ldo;
            #pragma unroll
            for (int nt = 0; nt < 8; ++nt) {
                const int gn = bn * BN + wn * 64 + nt * 8 + 2 * r;
                float c0 = acc[mt][nt][2 * h + 0];
                float c1 = acc[mt][nt][2 * h + 1];
                if constexpr (EPI == 1 || EPI == 3) {
                    c0 = fmaxf(c0 + bv, 0.f);
                    c1 = fmaxf(c1 + bv, 0.f);
                } else if constexpr (EPI == 2) {
                    c0 = fmaxf(c0 + bias[gn], 0.f);
                    c1 = fmaxf(c1 + bias[gn + 1], 0.f);
                }
                if constexpr (EPI == 3) {
                    const float* rp = res + (long long)row * ldo + gn;
                    c0 += rp[0]; c1 += rp[1];
                }
                if constexpr (OBF) {
                    __nv_bfloat162 v; v.x = bfr(c0); v.y = bfr(c1);
                    *(__nv_bfloat162*)((__nv_bfloat16*)outv + obase + gn) = v;
                } else {
                    float2 v; v.x = c0; v.y = c1;
                    *(float2*)((float*)outv + obase + gn) = v;
                }
            }
        }
    }
}

// ---------------- x transpose: [B,C,T] fp32 -> [B,T,C] bf16 ------------------
__global__ void __launch_bounds__(256, 4)
transpose_x(const float* __restrict__ x, __nv_bfloat16* __restrict__ xt)
{
    __shared__ float s[32][33];
    const int bz = blockIdx.z;
    const float* xp = x + (size_t)bz * NC * NT;
    __nv_bfloat16* op = xt + (size_t)bz * NT * NC;
    const int c0 = blockIdx.y * 32, t0 = blockIdx.x * 32;
    const int tid = threadIdx.x;
    {
        const int c = tid >> 3, tq = (tid & 7) * 4;
        float4 v = *(const float4*)&xp[(size_t)(c0 + c) * NT + t0 + tq];
        s[c][tq + 0] = v.x; s[c][tq + 1] = v.y;
        s[c][tq + 2] = v.z; s[c][tq + 3] = v.w;
    }
    __syncthreads();
    {
        const int t = tid >> 3, cb = (tid & 7) * 4;
        __nv_bfloat162 u0, u1;
        u0.x = bfr(s[cb + 0][t]); u0.y = bfr(s[cb + 1][t]);
        u1.x = bfr(s[cb + 2][t]); u1.y = bfr(s[cb + 3][t]);
        __nv_bfloat16* o = &op[(size_t)(t0 + t) * NC + c0 + cb];
        *(__nv_bfloat162*)(o + 0) = u0;
        *(__nv_bfloat162*)(o + 2) = u1;
    }
}

// ---------------- prep: all 4 weights -> bf16, stack theta/phi bias ----------
__global__ void __launch_bounds__(256, 8)
prep(const float* __restrict__ w0, const float* __restrict__ w1,
     const float* __restrict__ w2, const float* __restrict__ w3,
     const float* __restrict__ bt, const float* __restrict__ bp,
     __nv_bfloat16* __restrict__ wo, float* __restrict__ bqk)
{
    const int i = blockIdx.x * 256 + threadIdx.x;   // [0, 262144)
    const int idx = i * 4;
    const float* srcs[4] = {w0, w1, w2, w3};
    const float* sp = srcs[idx >> 18];
    float4 v = *(const float4*)(sp + (idx & 0x3FFFF));
    __nv_bfloat162 a, b;
    a.x = bfr(v.x); a.y = bfr(v.y);
    b.x = bfr(v.z); b.y = bfr(v.w);
    *(__nv_bfloat162*)(wo + idx)     = a;
    *(__nv_bfloat162*)(wo + idx + 2) = b;
    if (i < 2 * NC) bqk[i] = (i < NC) ? bt[i] : bp[i - NC];
}

// ---------------- softmax: fp32 scores row -> bf16 attn row ------------------
__global__ void __launch_bounds__(256, 4)
softmax2048(const float* __restrict__ S, __nv_bfloat16* __restrict__ P)
{
    const size_t roff = ((size_t)blockIdx.y * NT + blockIdx.x) * NT;
    const float* row = S + roff;
    __nv_bfloat16* prow = P + roff;
    const int tid = threadIdx.x;
    const int warp = tid >> 5, lane = tid & 31;

    float4 v0 = ((const float4*)row)[tid];
    float4 v1 = ((const float4*)row)[tid + 256];

    float mx = fmaxf(fmaxf(fmaxf(v0.x, v0.y), fmaxf(v0.z, v0.w)),
                     fmaxf(fmaxf(v1.x, v1.y), fmaxf(v1.z, v1.w)));
    #pragma unroll
    for (int o = 16; o; o >>= 1) mx = fmaxf(mx, __shfl_xor_sync(0xffffffffu, mx, o));

    __shared__ float sm[8], ss[8];
    if (!lane) sm[warp] = mx;
    __syncthreads();
    mx = sm[0];
    #pragma unroll
    for (int i = 1; i < 8; i++) mx = fmaxf(mx, sm[i]);

    v0.x = __expf(v0.x - mx); v0.y = __expf(v0.y - mx);
    v0.z = __expf(v0.z - mx); v0.w = __expf(v0.w - mx);
    v1.x = __expf(v1.x - mx); v1.y = __expf(v1.y - mx);
    v1.z = __expf(v1.z - mx); v1.w = __expf(v1.w - mx);

    float s = v0.x + v0.y + v0.z + v0.w + v1.x + v1.y + v1.z + v1.w;
    #pragma unroll
    for (int o = 16; o; o >>= 1) s += __shfl_xor_sync(0xffffffffu, s, o);
    if (!lane) ss[warp] = s;
    __syncthreads();
    s = ss[0];
    #pragma unroll
    for (int i = 1; i < 8; i++) s += ss[i];

    const float inv = 1.0f / s;
    __nv_bfloat162 a0, a1, b0, b1;
    a0.x = bfr(v0.x * inv); a0.y = bfr(v0.y * inv);
    a1.x = bfr(v0.z * inv); a1.y = bfr(v0.w * inv);
    b0.x = bfr(v1.x * inv); b0.y = bfr(v1.y * inv);
    b1.x = bfr(v1.z * inv); b1.y = bfr(v1.w * inv);
    ((__nv_bfloat162*)prow)[2 * tid + 0]   = a0;
    ((__nv_bfloat162*)prow)[2 * tid + 1]   = a1;
    ((__nv_bfloat162*)prow)[2 * (tid + 256) + 0] = b0;
    ((__nv_bfloat162*)prow)[2 * (tid + 256) + 1] = b1;
}

// ---------------- launch ----------------------------------------------------
extern "C" void kernel_launch(void* const* d_in, const int* in_sizes, int n_in,
                              void* d_out, int out_size)
{
    const float* x       = (const float*)d_in[0];
    const float* w_theta = (const float*)d_in[1];
    const float* b_theta = (const float*)d_in[2];
    const float* w_phi   = (const float*)d_in[3];
    const float* b_phi   = (const float*)d_in[4];
    const float* w_g     = (const float*)d_in[5];
    const float* b_g     = (const float*)d_in[6];
    const float* w_w     = (const float*)d_in[7];
    const float* b_w     = (const float*)d_in[8];

    void *pxt, *pqk, *pg, *pf, *pa, *ps, *pw, *pb;
    cudaGetSymbolAddress(&pxt, g_xt);
    cudaGetSymbolAddress(&pqk, g_qk);
    cudaGetSymbolAddress(&pg,  g_g);
    cudaGetSymbolAddress(&pf,  g_feat);
    cudaGetSymbolAddress(&pa,  g_attn);
    cudaGetSymbolAddress(&ps,  g_sc);
    cudaGetSymbolAddress(&pw,  g_wbf);
    cudaGetSymbolAddress(&pb,  g_bqk);
    __nv_bfloat16* xt   = (__nv_bfloat16*)pxt;
    __nv_bfloat16* thph = (__nv_bfloat16*)pqk;
    __nv_bfloat16* gg   = (__nv_bfloat16*)pg;
    __nv_bfloat16* ft   = (__nv_bfloat16*)pf;
    __nv_bfloat16* attn = (__nv_bfloat16*)pa;
    float*         sc   = (float*)ps;
    __nv_bfloat16* wbf  = (__nv_bfloat16*)pw;
    float*         bqk  = (float*)pb;
    __nv_bfloat16* wG = wbf + 2 * (size_t)NC * NC;
    __nv_bfloat16* wW = wbf + 3 * (size_t)NC * NC;

    const long long sCT = (long long)NC * NT;
    const long long sTT = (long long)NT * NT;
    const long long sQK = (long long)NT * 2 * NC;

    auto kconvT = gemm_bf<2, true >;   // stacked theta/phi: col bias
    auto kconvG = gemm_bf<1, true >;   // g: row bias
    auto kscore = gemm_bf<0, false>;   // scores fp32
    auto kfeat  = gemm_bf<0, true >;   // feat^T = attn @ g^T
    auto kfinal = gemm_bf<3, false>;   // relu(W.f+b)+x, fp32 out

    const int SMEM = 3 * (10240 + 10240);   // 61440
    cudaFuncSetAttribute(kconvT, cudaFuncAttributeMaxDynamicSharedMemorySize, SMEM);
    cudaFuncSetAttribute(kconvG, cudaFuncAttributeMaxDynamicSharedMemorySize, SMEM);
    cudaFuncSetAttribute(kscore, cudaFuncAttributeMaxDynamicSharedMemorySize, SMEM);
    cudaFuncSetAttribute(kfeat,  cudaFuncAttributeMaxDynamicSharedMemorySize, SMEM);
    cudaFuncSetAttribute(kfinal, cudaFuncAttributeMaxDynamicSharedMemorySize, SMEM);

    dim3 blk(256);

    // 0) weights -> bf16 (+ stacked bias); x -> x^T bf16
    prep<<<1024, blk>>>(w_theta, w_phi, w_g, w_w, b_theta, b_phi, wbf, bqk);
    transpose_x<<<dim3(NT / 32, NC / 32, NB), blk>>>(x, xt);

    // 1) thph[t, 0:1024] = relu(xt . [Wt|Wp]^T + [bt|bp])   (M=T, N=2C)
    kconvT<<<dim3(2 * NC / 128, NT / 128, NB), blk, SMEM>>>(
        xt, wbf, thph, NC, NC, 2 * NC, NC, sCT, 0, sQK, bqk, nullptr, 0);

    // 2) g[o,t] = relu(Wg . x + b)                           (M=C, N=T)
    kconvG<<<dim3(NT / 128, NC / 128, NB), blk, SMEM>>>(
        wG, xt, gg, NC, NC, NT, NC, 0, sCT, sCT, b_g, nullptr, 0);

    // 3) scores[i,j] = theta_i . phi_j                       (M=T, N=T) fp32
    kscore<<<dim3(NT / 128, NT / 128, NB), blk, SMEM>>>(
        thph, thph + NC, sc, 2 * NC, 2 * NC, NT, NC, sQK, sQK, sTT,
        nullptr, nullptr, 0);

    // 4) softmax over j -> bf16 attn
    softmax2048<<<dim3(NT, NB), blk>>>(sc, attn);

    // 5) feat^T[i,c] = sum_j attn[i,j] g[c,j]                (M=T, N=C, K=T)
    kfeat<<<dim3(NC / 128, NT / 128, NB), blk, SMEM>>>(
        attn, gg, ft, NT, NT, NC, NT, sTT, sCT, sCT, nullptr, nullptr, 0);

    // 6) out = relu(Ww . feat + b) + x                       (M=C, N=T)
    kfinal<<<dim3(NT / 128, NC / 128, NB), blk, SMEM>>>(
        wW, ft, d_out, NC, NC, NT, NC, 0, sCT, sCT, b_w, x, sCT);
}

// round 9
// speedup vs baseline: 1.7817x; 1.0937x over previous
#include <cuda_runtime.h>
#include <cuda_bf16.h>
#include <cstdint>

// Problem constants (fixed by the reference: B=8, C=512, T=2048)
#define NB 8
#define NC 512
#define NT 2048

// ---------------- scratch (device globals; no allocation allowed) ----------
__device__ __nv_bfloat16 g_xt  [(size_t)NB * NT * NC];      // x^T [B,T,C]
__device__ __nv_bfloat16 g_qk  [(size_t)NB * NT * 2 * NC];  // theta^T || phi^T [B,T,2C]
__device__ __nv_bfloat16 g_g   [(size_t)NB * NC * NT];      // g [B,C,T]
__device__ __nv_bfloat16 g_feat[(size_t)NB * NT * NC];      // feat^T [B,T,C]
__device__ __nv_bfloat16 g_attn[(size_t)NB * NT * NT];      // attn [B,T,T]
__device__ float         g_sc  [(size_t)NB * NT * NT];      // scores [B,T,T] fp32
__device__ __nv_bfloat16 g_wbf [4 * (size_t)NC * NC];       // wT|wP|wG|wW bf16
__device__ float         g_bqk [2 * NC];                    // b_theta || b_phi

// ---------------- helpers ---------------------------------------------------
__device__ __forceinline__ uint32_t smem_u32(const void* p) {
    return (uint32_t)__cvta_generic_to_shared(p);
}
__device__ __forceinline__ void cpa16u(uint32_t dst, const void* src) {
    asm volatile("cp.async.cg.shared.global [%0], [%1], 16;" :: "r"(dst), "l"(src));
}
__device__ __forceinline__ void cpa_commit() {
    asm volatile("cp.async.commit_group;" ::: "memory");
}
template<int N>
__device__ __forceinline__ void cpa_wait() {
    asm volatile("cp.async.wait_group %0;" :: "n"(N) : "memory");
}
__device__ __forceinline__ void ldsm4(uint32_t* r, uint32_t addr) {
    asm volatile("ldmatrix.sync.aligned.m8n8.x4.shared.b16 {%0,%1,%2,%3}, [%4];"
                 : "=r"(r[0]), "=r"(r[1]), "=r"(r[2]), "=r"(r[3]) : "r"(addr));
}
__device__ __forceinline__ void mma16(float* d, const uint32_t* a, const uint32_t* b) {
    asm volatile(
        "mma.sync.aligned.m16n8k16.row.col.f32.bf16.bf16.f32 "
        "{%0,%1,%2,%3}, {%4,%5,%6,%7}, {%8,%9}, {%0,%1,%2,%3};"
        : "+f"(d[0]), "+f"(d[1]), "+f"(d[2]), "+f"(d[3])
        : "r"(a[0]), "r"(a[1]), "r"(a[2]), "r"(a[3]), "r"(b[0]), "r"(b[1]));
}
__device__ __forceinline__ __nv_bfloat16 bfr(float f) { return __float2bfloat16_rn(f); }

// ---------------- BF16 GEMM: C[M,N] = sum_k A[m,k] * B[n,k] ------------------
// A: [M,K] bf16 (k contiguous), B: [N,K] bf16 (k contiguous)
// EPI: 0 plain | 1 relu(acc+bias[m]) | 2 relu(acc+bias[n]) | 3 relu(acc+bias[m])+res
// OBF: store bf16 (else fp32).
// CTA tile 128x128x64, 8 warps of 32x64, 2-stage cp.async, 2 CTAs/SM.
template<int EPI, bool OBF>
__global__ void __launch_bounds__(256, 2)
gemm_bf(const __nv_bfloat16* __restrict__ A, const __nv_bfloat16* __restrict__ B,
        void* __restrict__ outv, int lda, int ldb, int ldo, int K,
        long long sA, long long sB, long long sO,
        const float* __restrict__ bias,
        const float* __restrict__ res, long long sR)
{
    constexpr int BM = 128, BN = 128, BK = 64;
    constexpr int LDE = 72;                 // smem row stride (144 B)
    constexpr int A_BYT = BM * LDE * 2;     // 18432
    constexpr int B_BYT = BN * LDE * 2;     // 18432

    extern __shared__ char dsm[];
    const uint32_t smA = smem_u32(dsm);                 // [2][A_BYT]
    const uint32_t smB = smA + 2 * A_BYT;               // [2][B_BYT]

    const int tid = threadIdx.x;
    const int bn = blockIdx.x, bm = blockIdx.y, bz = blockIdx.z;
    const int warp = tid >> 5, lane = tid & 31;
    const int wm = warp >> 1, wn = warp & 1;     // 4 x 2 warps, 32x64 each
    const int r = lane & 3, q = lane >> 2;

    A += (long long)bz * sA + (long long)bm * BM * lda;
    B += (long long)bz * sB + (long long)bn * BN * ldb;
    if constexpr (EPI == 3) res += (long long)bz * sR;

    const int rowA = (lane & 7) + ((lane >> 3) & 1) * 8;   // bit3 = m-high
    const int kcA  = ((lane >> 4) & 1) * 8;                // bit4 = k-high
    const int rowB = (lane & 7) + ((lane >> 4) & 1) * 8;   // bit4 = n-high
    const int kcB  = ((lane >> 3) & 1) * 8;                // bit3 = k-high

    float acc[2][8][4];
    #pragma unroll
    for (int i = 0; i < 2; i++)
        #pragma unroll
        for (int j = 0; j < 8; j++)
            #pragma unroll
            for (int c = 0; c < 4; c++) acc[i][j][c] = 0.f;

    auto load_stage = [&](int kt, int sb) {
        const char* Ag = (const char*)A + (long long)kt * BK * 2;
        const char* Bg = (const char*)B + (long long)kt * BK * 2;
        const uint32_t as = smA + sb * A_BYT;
        const uint32_t bs = smB + sb * B_BYT;
        #pragma unroll
        for (int i = 0; i < 4; i++) {           // A: 128 rows x 128B = 1024 chunks
            const int id = tid + i * 256;
            const int row = id >> 3, c = (id & 7) * 16;
            cpa16u(as + row * 144 + c, Ag + (long long)row * lda * 2 + c);
        }
        #pragma unroll
        for (int i = 0; i < 4; i++) {           // B: 128 rows x 128B
            const int id = tid + i * 256;
            const int row = id >> 3, c = (id & 7) * 16;
            cpa16u(bs + row * 144 + c, Bg + (long long)row * ldb * 2 + c);
        }
    };

    const int nk = K / BK;
    load_stage(0, 0); cpa_commit();

    for (int kt = 0; kt < nk; ++kt) {
        cpa_wait<0>();            // stage kt fully resident (this thread)
        __syncthreads();          // all threads see it; prev compute done
        if (kt + 1 < nk) { load_stage(kt + 1, (kt + 1) & 1); cpa_commit(); }

        const uint32_t aA = smA + (kt & 1) * A_BYT;
        const uint32_t aB = smB + (kt & 1) * B_BYT;

        #pragma unroll
        for (int ks = 0; ks < 4; ++ks) {
            const int kk = ks * 16;
            uint32_t af[2][4], bf[8][2];
            #pragma unroll
            for (int mt = 0; mt < 2; ++mt)
                ldsm4(af[mt], aA + ((wm * 32 + mt * 16 + rowA) * LDE + kcA + kk) * 2);
            #pragma unroll
            for (int ntp = 0; ntp < 4; ++ntp) {
                uint32_t t4[4];
                ldsm4(t4, aB + ((wn * 64 + ntp * 16 + rowB) * LDE + kcB + kk) * 2);
                bf[2 * ntp + 0][0] = t4[0]; bf[2 * ntp + 0][1] = t4[1];
                bf[2 * ntp + 1][0] = t4[2]; bf[2 * ntp + 1][1] = t4[3];
            }
            #pragma unroll
            for (int mt = 0; mt < 2; ++mt)
                #pragma unroll
                for (int nt = 0; nt < 8; ++nt)
                    mma16(acc[mt][nt], af[mt], bf[nt]);
        }
    }

    // ---- epilogue: c0,c1 -> (row q, cols 2r,2r+1); c2,c3 -> row q+8 ---------
    #pragma unroll
    for (int mt = 0; mt < 2; ++mt) {
        #pragma unroll
        for (int h = 0; h < 2; ++h) {
            const int row = bm * BM + wm * 32 + mt * 16 + h * 8 + q;
            float bv = 0.f;
            if constexpr (EPI == 1 || EPI == 3) bv = bias[row];
            const long long obase = (long long)bz * sO + (long long)row * ldo;
            #pragma unroll
            for (int nt = 0; nt < 8; ++nt) {
                const int gn = bn * BN + wn * 64 + nt * 8 + 2 * r;
                float c0 = acc[mt][nt][2 * h + 0];
                float c1 = acc[mt][nt][2 * h + 1];
                if constexpr (EPI == 1 || EPI == 3) {
                    c0 = fmaxf(c0 + bv, 0.f);
                    c1 = fmaxf(c1 + bv, 0.f);
                } else if constexpr (EPI == 2) {
                    c0 = fmaxf(c0 + bias[gn], 0.f);
                    c1 = fmaxf(c1 + bias[gn + 1], 0.f);
                }
                if constexpr (EPI == 3) {
                    const float* rp = res + (long long)row * ldo + gn;
                    c0 += rp[0]; c1 += rp[1];
                }
                if constexpr (OBF) {
                    __nv_bfloat162 v; v.x = bfr(c0); v.y = bfr(c1);
                    *(__nv_bfloat162*)((__nv_bfloat16*)outv + obase + gn) = v;
                } else {
                    float2 v; v.x = c0; v.y = c1;
                    *(float2*)((float*)outv + obase + gn) = v;
                }
            }
        }
    }
}

// ---------------- x transpose: [B,C,T] fp32 -> [B,T,C] bf16 ------------------
__global__ void __launch_bounds__(256, 4)
transpose_x(const float* __restrict__ x, __nv_bfloat16* __restrict__ xt)
{
    __shared__ float s[32][33];
    const int bz = blockIdx.z;
    const float* xp = x + (size_t)bz * NC * NT;
    __nv_bfloat16* op = xt + (size_t)bz * NT * NC;
    const int c0 = blockIdx.y * 32, t0 = blockIdx.x * 32;
    const int tid = threadIdx.x;
    {
        const int c = tid >> 3, tq = (tid & 7) * 4;
        float4 v = *(const float4*)&xp[(size_t)(c0 + c) * NT + t0 + tq];
        s[c][tq + 0] = v.x; s[c][tq + 1] = v.y;
        s[c][tq + 2] = v.z; s[c][tq + 3] = v.w;
    }
    __syncthreads();
    {
        const int t = tid >> 3, cb = (tid & 7) * 4;
        __nv_bfloat162 u0, u1;
        u0.x = bfr(s[cb + 0][t]); u0.y = bfr(s[cb + 1][t]);
        u1.x = bfr(s[cb + 2][t]); u1.y = bfr(s[cb + 3][t]);
        __nv_bfloat16* o = &op[(size_t)(t0 + t) * NC + c0 + cb];
        *(__nv_bfloat162*)(o + 0) = u0;
        *(__nv_bfloat162*)(o + 2) = u1;
    }
}

// ---------------- prep: all 4 weights -> bf16, stack theta/phi bias ----------
__global__ void __launch_bounds__(256, 8)
prep(const float* __restrict__ w0, const float* __restrict__ w1,
     const float* __restrict__ w2, const float* __restrict__ w3,
     const float* __restrict__ bt, const float* __restrict__ bp,
     __nv_bfloat16* __restrict__ wo, float* __restrict__ bqk)
{
    const int i = blockIdx.x * 256 + threadIdx.x;   // [0, 262144)
    const int idx = i * 4;
    const float* srcs[4] = {w0, w1, w2, w3};
    const float* sp = srcs[idx >> 18];
    float4 v = *(const float4*)(sp + (idx & 0x3FFFF));
    __nv_bfloat162 a, b;
    a.x = bfr(v.x); a.y = bfr(v.y);
    b.x = bfr(v.z); b.y = bfr(v.w);
    *(__nv_bfloat162*)(wo + idx)     = a;
    *(__nv_bfloat162*)(wo + idx + 2) = b;
    if (i < 2 * NC) bqk[i] = (i < NC) ? bt[i] : bp[i - NC];
}

// ---------------- softmax: fp32 scores row -> bf16 attn row ------------------
__global__ void __launch_bounds__(256, 4)
softmax2048(const float* __restrict__ S, __nv_bfloat16* __restrict__ P)
{
    const size_t roff = ((size_t)blockIdx.y * NT + blockIdx.x) * NT;
    const float* row = S + roff;
    __nv_bfloat16* prow = P + roff;
    const int tid = threadIdx.x;
    const int warp = tid >> 5, lane = tid & 31;

    float4 v0 = ((const float4*)row)[tid];
    float4 v1 = ((const float4*)row)[tid + 256];

    float mx = fmaxf(fmaxf(fmaxf(v0.x, v0.y), fmaxf(v0.z, v0.w)),
                     fmaxf(fmaxf(v1.x, v1.y), fmaxf(v1.z, v1.w)));
    #pragma unroll
    for (int o = 16; o; o >>= 1) mx = fmaxf(mx, __shfl_xor_sync(0xffffffffu, mx, o));

    __shared__ float sm[8], ss[8];
    if (!lane) sm[warp] = mx;
    __syncthreads();
    mx = sm[0];
    #pragma unroll
    for (int i = 1; i < 8; i++) mx = fmaxf(mx, sm[i]);

    v0.x = __expf(v0.x - mx); v0.y = __expf(v0.y - mx);
    v0.z = __expf(v0.z - mx); v0.w = __expf(v0.w - mx);
    v1.x = __expf(v1.x - mx); v1.y = __expf(v1.y - mx);
    v1.z = __expf(v1.z - mx); v1.w = __expf(v1.w - mx);

    float s = v0.x + v0.y + v0.z + v0.w + v1.x + v1.y + v1.z + v1.w;
    #pragma unroll
    for (int o = 16; o; o >>= 1) s += __shfl_xor_sync(0xffffffffu, s, o);
    if (!lane) ss[warp] = s;
    __syncthreads();
    s = ss[0];
    #pragma unroll
    for (int i = 1; i < 8; i++) s += ss[i];

    const float inv = 1.0f / s;
    __nv_bfloat162 a0, a1, b0, b1;
    a0.x = bfr(v0.x * inv); a0.y = bfr(v0.y * inv);
    a1.x = bfr(v0.z * inv); a1.y = bfr(v0.w * inv);
    b0.x = bfr(v1.x * inv); b0.y = bfr(v1.y * inv);
    b1.x = bfr(v1.z * inv); b1.y = bfr(v1.w * inv);
    ((__nv_bfloat162*)prow)[2 * tid + 0]   = a0;
    ((__nv_bfloat162*)prow)[2 * tid + 1]   = a1;
    ((__nv_bfloat162*)prow)[2 * (tid + 256) + 0] = b0;
    ((__nv_bfloat162*)prow)[2 * (tid + 256) + 1] = b1;
}

// ---------------- launch ----------------------------------------------------
extern "C" void kernel_launch(void* const* d_in, const int* in_sizes, int n_in,
                              void* d_out, int out_size)
{
    const float* x       = (const float*)d_in[0];
    const float* w_theta = (const float*)d_in[1];
    const float* b_theta = (const float*)d_in[2];
    const float* w_phi   = (const float*)d_in[3];
    const float* b_phi   = (const float*)d_in[4];
    const float* w_g     = (const float*)d_in[5];
    const float* b_g     = (const float*)d_in[6];
    const float* w_w     = (const float*)d_in[7];
    const float* b_w     = (const float*)d_in[8];

    void *pxt, *pqk, *pg, *pf, *pa, *ps, *pw, *pb;
    cudaGetSymbolAddress(&pxt, g_xt);
    cudaGetSymbolAddress(&pqk, g_qk);
    cudaGetSymbolAddress(&pg,  g_g);
    cudaGetSymbolAddress(&pf,  g_feat);
    cudaGetSymbolAddress(&pa,  g_attn);
    cudaGetSymbolAddress(&ps,  g_sc);
    cudaGetSymbolAddress(&pw,  g_wbf);
    cudaGetSymbolAddress(&pb,  g_bqk);
    __nv_bfloat16* xt   = (__nv_bfloat16*)pxt;
    __nv_bfloat16* thph = (__nv_bfloat16*)pqk;
    __nv_bfloat16* gg   = (__nv_bfloat16*)pg;
    __nv_bfloat16* ft   = (__nv_bfloat16*)pf;
    __nv_bfloat16* attn = (__nv_bfloat16*)pa;
    float*         sc   = (float*)ps;
    __nv_bfloat16* wbf  = (__nv_bfloat16*)pw;
    float*         bqk  = (float*)pb;
    __nv_bfloat16* wG = wbf + 2 * (size_t)NC * NC;
    __nv_bfloat16* wW = wbf + 3 * (size_t)NC * NC;

    const long long sCT = (long long)NC * NT;
    const long long sTT = (long long)NT * NT;
    const long long sQK = (long long)NT * 2 * NC;

    auto kconvT = gemm_bf<2, true >;   // stacked theta/phi: col bias
    auto kconvG = gemm_bf<1, true >;   // g: row bias
    auto kscore = gemm_bf<0, false>;   // scores fp32
    auto kfeat  = gemm_bf<0, true >;   // feat^T = attn @ g^T
    auto kfinal = gemm_bf<3, false>;   // relu(W.f+b)+x, fp32 out

    const int SMEM = 2 * (18432 + 18432);   // 73728
    cudaFuncSetAttribute(kconvT, cudaFuncAttributeMaxDynamicSharedMemorySize, SMEM);
    cudaFuncSetAttribute(kconvG, cudaFuncAttributeMaxDynamicSharedMemorySize, SMEM);
    cudaFuncSetAttribute(kscore, cudaFuncAttributeMaxDynamicSharedMemorySize, SMEM);
    cudaFuncSetAttribute(kfeat,  cudaFuncAttributeMaxDynamicSharedMemorySize, SMEM);
    cudaFuncSetAttribute(kfinal, cudaFuncAttributeMaxDynamicSharedMemorySize, SMEM);

    dim3 blk(256);

    // 0) weights -> bf16 (+ stacked bias); x -> x^T bf16
    prep<<<1024, blk>>>(w_theta, w_phi, w_g, w_w, b_theta, b_phi, wbf, bqk);
    transpose_x<<<dim3(NT / 32, NC / 32, NB), blk>>>(x, xt);

    // 1) thph[t, 0:1024] = relu(xt . [Wt|Wp]^T + [bt|bp])   (M=T, N=2C)
    kconvT<<<dim3(2 * NC / 128, NT / 128, NB), blk, SMEM>>>(
        xt, wbf, thph, NC, NC, 2 * NC, NC, sCT, 0, sQK, bqk, nullptr, 0);

    // 2) g[o,t] = relu(Wg . x + b)                           (M=C, N=T)
    kconvG<<<dim3(NT / 128, NC / 128, NB), blk, SMEM>>>(
        wG, xt, gg, NC, NC, NT, NC, 0, sCT, sCT, b_g, nullptr, 0);

    // 3) scores[i,j] = theta_i . phi_j                       (M=T, N=T) fp32
    kscore<<<dim3(NT / 128, NT / 128, NB), blk, SMEM>>>(
        thph, thph + NC, sc, 2 * NC, 2 * NC, NT, NC, sQK, sQK, sTT,
        nullptr, nullptr, 0);

    // 4) softmax over j -> bf16 attn
    softmax2048<<<dim3(NT, NB), blk>>>(sc, attn);

    // 5) feat^T[i,c] = sum_j attn[i,j] g[c,j]                (M=T, N=C, K=T)
    kfeat<<<dim3(NC / 128, NT / 128, NB), blk, SMEM>>>(
        attn, gg, ft, NT, NT, NC, NT, sTT, sCT, sCT, nullptr, nullptr, 0);

    // 6) out = relu(Ww . feat + b) + x                       (M=C, N=T)
    kfinal<<<dim3(NT / 128, NC / 128, NB), blk, SMEM>>>(
        wW, ft, d_out, NC, NC, NT, NC, 0, sCT, sCT, b_w, x, sCT);
}

// round 10
// speedup vs baseline: 1.8246x; 1.0241x over previous
#include <cuda_runtime.h>
#include <cuda_bf16.h>
#include <cstdint>

// Problem constants (fixed by the reference: B=8, C=512, T=2048)
#define NB 8
#define NC 512
#define NT 2048

// ---------------- scratch (device globals; no allocation allowed) ----------
__device__ __nv_bfloat16 g_xt  [(size_t)NB * NT * NC];      // x^T [B,T,C]
__device__ __nv_bfloat16 g_qk  [(size_t)NB * NT * 2 * NC];  // theta^T || phi^T [B,T,2C]
__device__ __nv_bfloat16 g_g   [(size_t)NB * NC * NT];      // g [B,C,T]
__device__ __nv_bfloat16 g_feat[(size_t)NB * NT * NC];      // feat^T [B,T,C]
__device__ __nv_bfloat16 g_attn[(size_t)NB * NT * NT];      // attn [B,T,T]
__device__ float         g_sc  [(size_t)NB * NT * NT];      // scores [B,T,T] fp32
__device__ __nv_bfloat16 g_wbf [4 * (size_t)NC * NC];       // wT|wP|wG|wW bf16
__device__ float         g_bqk [2 * NC];                    // b_theta || b_phi

// ---------------- helpers ---------------------------------------------------
__device__ __forceinline__ uint32_t smem_u32(const void* p) {
    return (uint32_t)__cvta_generic_to_shared(p);
}
__device__ __forceinline__ void cpa16u(uint32_t dst, const void* src) {
    asm volatile("cp.async.cg.shared.global [%0], [%1], 16;" :: "r"(dst), "l"(src));
}
__device__ __forceinline__ void cpa_commit() {
    asm volatile("cp.async.commit_group;" ::: "memory");
}
template<int N>
__device__ __forceinline__ void cpa_wait() {
    asm volatile("cp.async.wait_group %0;" :: "n"(N) : "memory");
}
__device__ __forceinline__ void ldsm4(uint32_t* r, uint32_t addr) {
    asm volatile("ldmatrix.sync.aligned.m8n8.x4.shared.b16 {%0,%1,%2,%3}, [%4];"
                 : "=r"(r[0]), "=r"(r[1]), "=r"(r[2]), "=r"(r[3]) : "r"(addr));
}
__device__ __forceinline__ void mma16(float* d, const uint32_t* a, const uint32_t* b) {
    asm volatile(
        "mma.sync.aligned.m16n8k16.row.col.f32.bf16.bf16.f32 "
        "{%0,%1,%2,%3}, {%4,%5,%6,%7}, {%8,%9}, {%0,%1,%2,%3};"
        : "+f"(d[0]), "+f"(d[1]), "+f"(d[2]), "+f"(d[3])
        : "r"(a[0]), "r"(a[1]), "r"(a[2]), "r"(a[3]), "r"(b[0]), "r"(b[1]));
}
__device__ __forceinline__ __nv_bfloat16 bfr(float f) { return __float2bfloat16_rn(f); }

// ---------------- BF16 GEMM: C[M,N] = sum_k A[m,k] * B[n,k] ------------------
// A: [M,K] bf16 (k contiguous), B: [N,K] bf16 (k contiguous)
// EPI: 0 plain | 1 relu(acc+bias[m]) | 2 relu(acc+bias[n]) | 3 relu(acc+bias[m])+res
// OBF: store bf16 (else fp32).
// CTA tile 128x64x64, 4 warps of 32x64, 2-stage cp.async, 4 CTAs/SM.
// 4 independent barrier domains per SM break the lock-step stall correlation.
template<int EPI, bool OBF>
__global__ void __launch_bounds__(128, 4)
gemm_bf(const __nv_bfloat16* __restrict__ A, const __nv_bfloat16* __restrict__ B,
        void* __restrict__ outv, int lda, int ldb, int ldo, int K,
        long long sA, long long sB, long long sO,
        const float* __restrict__ bias,
        const float* __restrict__ res, long long sR)
{
    constexpr int BM = 128, BN = 64, BK = 64;
    constexpr int LDE = 72;                 // smem row stride (144 B)
    constexpr int A_BYT = BM * LDE * 2;     // 18432
    constexpr int B_BYT = BN * LDE * 2;     //  9216

    extern __shared__ char dsm[];
    const uint32_t smA = smem_u32(dsm);                 // [2][A_BYT]
    const uint32_t smB = smA + 2 * A_BYT;               // [2][B_BYT]

    const int tid = threadIdx.x;
    const int bn = blockIdx.x, bm = blockIdx.y, bz = blockIdx.z;
    const int warp = tid >> 5, lane = tid & 31;         // 4 warps, stacked in m
    const int r = lane & 3, q = lane >> 2;

    A += (long long)bz * sA + (long long)bm * BM * lda;
    B += (long long)bz * sB + (long long)bn * BN * ldb;
    if constexpr (EPI == 3) res += (long long)bz * sR;

    const int rowA = (lane & 7) + ((lane >> 3) & 1) * 8;   // bit3 = m-high
    const int kcA  = ((lane >> 4) & 1) * 8;                // bit4 = k-high
    const int rowB = (lane & 7) + ((lane >> 4) & 1) * 8;   // bit4 = n-high
    const int kcB  = ((lane >> 3) & 1) * 8;                // bit3 = k-high

    float acc[2][8][4];
    #pragma unroll
    for (int i = 0; i < 2; i++)
        #pragma unroll
        for (int j = 0; j < 8; j++)
            #pragma unroll
            for (int c = 0; c < 4; c++) acc[i][j][c] = 0.f;

    auto load_stage = [&](int kt, int sb) {
        const char* Ag = (const char*)A + (long long)kt * BK * 2;
        const char* Bg = (const char*)B + (long long)kt * BK * 2;
        const uint32_t as = smA + sb * A_BYT;
        const uint32_t bs = smB + sb * B_BYT;
        #pragma unroll
        for (int i = 0; i < 8; i++) {           // A: 128 rows x 128B = 1024 chunks
            const int id = tid + i * 128;
            const int row = id >> 3, c = (id & 7) * 16;
            cpa16u(as + row * 144 + c, Ag + (long long)row * lda * 2 + c);
        }
        #pragma unroll
        for (int i = 0; i < 4; i++) {           // B: 64 rows x 128B = 512 chunks
            const int id = tid + i * 128;
            const int row = id >> 3, c = (id & 7) * 16;
            cpa16u(bs + row * 144 + c, Bg + (long long)row * ldb * 2 + c);
        }
    };

    const int nk = K / BK;
    load_stage(0, 0); cpa_commit();

    for (int kt = 0; kt < nk; ++kt) {
        cpa_wait<0>();            // stage kt fully resident (this thread)
        __syncthreads();          // all threads see it; prev compute done
        if (kt + 1 < nk) { load_stage(kt + 1, (kt + 1) & 1); cpa_commit(); }

        const uint32_t aA = smA + (kt & 1) * A_BYT;
        const uint32_t aB = smB + (kt & 1) * B_BYT;

        #pragma unroll
        for (int ks = 0; ks < 4; ++ks) {
            const int kk = ks * 16;
            uint32_t af[2][4], bf[8][2];
            #pragma unroll
            for (int mt = 0; mt < 2; ++mt)
                ldsm4(af[mt], aA + ((warp * 32 + mt * 16 + rowA) * LDE + kcA + kk) * 2);
            #pragma unroll
            for (int ntp = 0; ntp < 4; ++ntp) {
                uint32_t t4[4];
                ldsm4(t4, aB + ((ntp * 16 + rowB) * LDE + kcB + kk) * 2);
                bf[2 * ntp + 0][0] = t4[0]; bf[2 * ntp + 0][1] = t4[1];
                bf[2 * ntp + 1][0] = t4[2]; bf[2 * ntp + 1][1] = t4[3];
            }
            #pragma unroll
            for (int mt = 0; mt < 2; ++mt)
                #pragma unroll
                for (int nt = 0; nt < 8; ++nt)
                    mma16(acc[mt][nt], af[mt], bf[nt]);
        }
    }

    // ---- epilogue: c0,c1 -> (row q, cols 2r,2r+1); c2,c3 -> row q+8 ---------
    #pragma unroll
    for (int mt = 0; mt < 2; ++mt) {
        #pragma unroll
        for (int h = 0; h < 2; ++h) {
            const int row = bm * BM + warp * 32 + mt * 16 + h * 8 + q;
            float bv = 0.f;
            if constexpr (EPI == 1 || EPI == 3) bv = bias[row];
            const long long obase = (long long)bz * sO + (long long)row * ldo;
            #pragma unroll
            for (int nt = 0; nt < 8; ++nt) {
                const int gn = bn * BN + nt * 8 + 2 * r;
                float c0 = acc[mt][nt][2 * h + 0];
                float c1 = acc[mt][nt][2 * h + 1];
                if constexpr (EPI == 1 || EPI == 3) {
                    c0 = fmaxf(c0 + bv, 0.f);
                    c1 = fmaxf(c1 + bv, 0.f);
                } else if constexpr (EPI == 2) {
                    c0 = fmaxf(c0 + bias[gn], 0.f);
                    c1 = fmaxf(c1 + bias[gn + 1], 0.f);
                }
                if constexpr (EPI == 3) {
                    const float* rp = res + (long long)row * ldo + gn;
                    c0 += rp[0]; c1 += rp[1];
                }
                if constexpr (OBF) {
                    __nv_bfloat162 v; v.x = bfr(c0); v.y = bfr(c1);
                    *(__nv_bfloat162*)((__nv_bfloat16*)outv + obase + gn) = v;
                } else {
                    float2 v; v.x = c0; v.y = c1;
                    *(float2*)((float*)outv + obase + gn) = v;
                }
            }
        }
    }
}

// ---------------- x transpose: [B,C,T] fp32 -> [B,T,C] bf16 ------------------
__global__ void __launch_bounds__(256, 4)
transpose_x(const float* __restrict__ x, __nv_bfloat16* __restrict__ xt)
{
    __shared__ float s[32][33];
    const int bz = blockIdx.z;
    const float* xp = x + (size_t)bz * NC * NT;
    __nv_bfloat16* op = xt + (size_t)bz * NT * NC;
    const int c0 = blockIdx.y * 32, t0 = blockIdx.x * 32;
    const int tid = threadIdx.x;
    {
        const int c = tid >> 3, tq = (tid & 7) * 4;
        float4 v = *(const float4*)&xp[(size_t)(c0 + c) * NT + t0 + tq];
        s[c][tq + 0] = v.x; s[c][tq + 1] = v.y;
        s[c][tq + 2] = v.z; s[c][tq + 3] = v.w;
    }
    __syncthreads();
    {
        const int t = tid >> 3, cb = (tid & 7) * 4;
        __nv_bfloat162 u0, u1;
        u0.x = bfr(s[cb + 0][t]); u0.y = bfr(s[cb + 1][t]);
        u1.x = bfr(s[cb + 2][t]); u1.y = bfr(s[cb + 3][t]);
        __nv_bfloat16* o = &op[(size_t)(t0 + t) * NC + c0 + cb];
        *(__nv_bfloat162*)(o + 0) = u0;
        *(__nv_bfloat162*)(o + 2) = u1;
    }
}

// ---------------- prep: all 4 weights -> bf16, stack theta/phi bias ----------
__global__ void __launch_bounds__(256, 8)
prep(const float* __restrict__ w0, const float* __restrict__ w1,
     const float* __restrict__ w2, const float* __restrict__ w3,
     const float* __restrict__ bt, const float* __restrict__ bp,
     __nv_bfloat16* __restrict__ wo, float* __restrict__ bqk)
{
    const int i = blockIdx.x * 256 + threadIdx.x;   // [0, 262144)
    const int idx = i * 4;
    const float* srcs[4] = {w0, w1, w2, w3};
    const float* sp = srcs[idx >> 18];
    float4 v = *(const float4*)(sp + (idx & 0x3FFFF));
    __nv_bfloat162 a, b;
    a.x = bfr(v.x); a.y = bfr(v.y);
    b.x = bfr(v.z); b.y = bfr(v.w);
    *(__nv_bfloat162*)(wo + idx)     = a;
    *(__nv_bfloat162*)(wo + idx + 2) = b;
    if (i < 2 * NC) bqk[i] = (i < NC) ? bt[i] : bp[i - NC];
}

// ---------------- softmax: fp32 scores row -> bf16 attn row ------------------
__global__ void __launch_bounds__(256, 4)
softmax2048(const float* __restrict__ S, __nv_bfloat16* __restrict__ P)
{
    const size_t roff = ((size_t)blockIdx.y * NT + blockIdx.x) * NT;
    const float* row = S + roff;
    __nv_bfloat16* prow = P + roff;
    const int tid = threadIdx.x;
    const int warp = tid >> 5, lane = tid & 31;

    float4 v0 = ((const float4*)row)[tid];
    float4 v1 = ((const float4*)row)[tid + 256];

    float mx = fmaxf(fmaxf(fmaxf(v0.x, v0.y), fmaxf(v0.z, v0.w)),
                     fmaxf(fmaxf(v1.x, v1.y), fmaxf(v1.z, v1.w)));
    #pragma unroll
    for (int o = 16; o; o >>= 1) mx = fmaxf(mx, __shfl_xor_sync(0xffffffffu, mx, o));

    __shared__ float sm[8], ss[8];
    if (!lane) sm[warp] = mx;
    __syncthreads();
    mx = sm[0];
    #pragma unroll
    for (int i = 1; i < 8; i++) mx = fmaxf(mx, sm[i]);

    v0.x = __expf(v0.x - mx); v0.y = __expf(v0.y - mx);
    v0.z = __expf(v0.z - mx); v0.w = __expf(v0.w - mx);
    v1.x = __expf(v1.x - mx); v1.y = __expf(v1.y - mx);
    v1.z = __expf(v1.z - mx); v1.w = __expf(v1.w - mx);

    float s = v0.x + v0.y + v0.z + v0.w + v1.x + v1.y + v1.z + v1.w;
    #pragma unroll
    for (int o = 16; o; o >>= 1) s += __shfl_xor_sync(0xffffffffu, s, o);
    if (!lane) ss[warp] = s;
    __syncthreads();
    s = ss[0];
    #pragma unroll
    for (int i = 1; i < 8; i++) s += ss[i];

    const float inv = 1.0f / s;
    __nv_bfloat162 a0, a1, b0, b1;
    a0.x = bfr(v0.x * inv); a0.y = bfr(v0.y * inv);
    a1.x = bfr(v0.z * inv); a1.y = bfr(v0.w * inv);
    b0.x = bfr(v1.x * inv); b0.y = bfr(v1.y * inv);
    b1.x = bfr(v1.z * inv); b1.y = bfr(v1.w * inv);
    ((__nv_bfloat162*)prow)[2 * tid + 0]   = a0;
    ((__nv_bfloat162*)prow)[2 * tid + 1]   = a1;
    ((__nv_bfloat162*)prow)[2 * (tid + 256) + 0] = b0;
    ((__nv_bfloat162*)prow)[2 * (tid + 256) + 1] = b1;
}

// ---------------- launch ----------------------------------------------------
extern "C" void kernel_launch(void* const* d_in, const int* in_sizes, int n_in,
                              void* d_out, int out_size)
{
    const float* x       = (const float*)d_in[0];
    const float* w_theta = (const float*)d_in[1];
    const float* b_theta = (const float*)d_in[2];
    const float* w_phi   = (const float*)d_in[3];
    const float* b_phi   = (const float*)d_in[4];
    const float* w_g     = (const float*)d_in[5];
    const float* b_g     = (const float*)d_in[6];
    const float* w_w     = (const float*)d_in[7];
    const float* b_w     = (const float*)d_in[8];

    void *pxt, *pqk, *pg, *pf, *pa, *ps, *pw, *pb;
    cudaGetSymbolAddress(&pxt, g_xt);
    cudaGetSymbolAddress(&pqk, g_qk);
    cudaGetSymbolAddress(&pg,  g_g);
    cudaGetSymbolAddress(&pf,  g_feat);
    cudaGetSymbolAddress(&pa,  g_attn);
    cudaGetSymbolAddress(&ps,  g_sc);
    cudaGetSymbolAddress(&pw,  g_wbf);
    cudaGetSymbolAddress(&pb,  g_bqk);
    __nv_bfloat16* xt   = (__nv_bfloat16*)pxt;
    __nv_bfloat16* thph = (__nv_bfloat16*)pqk;
    __nv_bfloat16* gg   = (__nv_bfloat16*)pg;
    __nv_bfloat16* ft   = (__nv_bfloat16*)pf;
    __nv_bfloat16* attn = (__nv_bfloat16*)pa;
    float*         sc   = (float*)ps;
    __nv_bfloat16* wbf  = (__nv_bfloat16*)pw;
    float*         bqk  = (float*)pb;
    __nv_bfloat16* wG = wbf + 2 * (size_t)NC * NC;
    __nv_bfloat16* wW = wbf + 3 * (size_t)NC * NC;

    const long long sCT = (long long)NC * NT;
    const long long sTT = (long long)NT * NT;
    const long long sQK = (long long)NT * 2 * NC;

    auto kconvT = gemm_bf<2, true >;   // stacked theta/phi: col bias
    auto kconvG = gemm_bf<1, true >;   // g: row bias
    auto kscore = gemm_bf<0, false>;   // scores fp32
    auto kfeat  = gemm_bf<0, true >;   // feat^T = attn @ g^T
    auto kfinal = gemm_bf<3, false>;   // relu(W.f+b)+x, fp32 out

    const int SMEM = 2 * (18432 + 9216);   // 55296 per CTA, 4 CTAs/SM
    cudaFuncSetAttribute(kconvT, cudaFuncAttributeMaxDynamicSharedMemorySize, SMEM);
    cudaFuncSetAttribute(kconvG, cudaFuncAttributeMaxDynamicSharedMemorySize, SMEM);
    cudaFuncSetAttribute(kscore, cudaFuncAttributeMaxDynamicSharedMemorySize, SMEM);
    cudaFuncSetAttribute(kfeat,  cudaFuncAttributeMaxDynamicSharedMemorySize, SMEM);
    cudaFuncSetAttribute(kfinal, cudaFuncAttributeMaxDynamicSharedMemorySize, SMEM);

    dim3 blk(256);
    dim3 gblk(128);

    // 0) weights -> bf16 (+ stacked bias); x -> x^T bf16
    prep<<<1024, blk>>>(w_theta, w_phi, w_g, w_w, b_theta, b_phi, wbf, bqk);
    transpose_x<<<dim3(NT / 32, NC / 32, NB), blk>>>(x, xt);

    // 1) thph[t, 0:1024] = relu(xt . [Wt|Wp]^T + [bt|bp])   (M=T, N=2C)
    kconvT<<<dim3(2 * NC / 64, NT / 128, NB), gblk, SMEM>>>(
        xt, wbf, thph, NC, NC, 2 * NC, NC, sCT, 0, sQK, bqk, nullptr, 0);

    // 2) g[o,t] = relu(Wg . x + b)                           (M=C, N=T)
    kconvG<<<dim3(NT / 64, NC / 128, NB), gblk, SMEM>>>(
        wG, xt, gg, NC, NC, NT, NC, 0, sCT, sCT, b_g, nullptr, 0);

    // 3) scores[i,j] = theta_i . phi_j                       (M=T, N=T) fp32
    kscore<<<dim3(NT / 64, NT / 128, NB), gblk, SMEM>>>(
        thph, thph + NC, sc, 2 * NC, 2 * NC, NT, NC, sQK, sQK, sTT,
        nullptr, nullptr, 0);

    // 4) softmax over j -> bf16 attn
    softmax2048<<<dim3(NT, NB), blk>>>(sc, attn);

    // 5) feat^T[i,c] = sum_j attn[i,j] g[c,j]                (M=T, N=C, K=T)
    kfeat<<<dim3(NC / 64, NT / 128, NB), gblk, SMEM>>>(
        attn, gg, ft, NT, NT, NC, NT, sTT, sCT, sCT, nullptr, nullptr, 0);

    // 6) out = relu(Ww . feat + b) + x                       (M=C, N=T)
    kfinal<<<dim3(NT / 64, NC / 128, NB), gblk, SMEM>>>(
        wW, ft, d_out, NC, NC, NT, NC, 0, sCT, sCT, b_w, x, sCT);
}